// round 14
// baseline (speedup 1.0000x reference)
#include <cuda_runtime.h>
#include <cstdint>
#include <math.h>

#define EMBED   256
#define HIDDEN  512
#define NB      64
#define LSTEPS  2048

// xp[t][n][h] scratch: 2048*64*512 floats = 256MB
__device__ float g_xp[(size_t)LSTEPS * NB * HIDDEN];

// ---- packed f32x2 helpers (Blackwell) ----
#define FMA_F32X2(acc, a, b) \
    asm("fma.rn.f32x2 %0, %1, %2, %0;" : "+l"(acc) : "l"(a), "l"(b))
#define PACK_F32X2(out, lo, hi) \
    asm("mov.b64 %0, {%1, %2};" : "=l"(out) : "f"(lo), "f"(hi))
#define UNPACK_F32X2(lo, hi, in) \
    asm("mov.b64 {%0, %1}, %2;" : "=f"(lo), "=f"(hi) : "l"(in))

// ============================================================================
// Phase 1: xp[l][n][j] = b_xh[j] + sum_d E[X[n][l]][d] * W_xh[d][j]
// (unchanged — passing, ~0.85ms)
// ============================================================================
#define BM 128
#define BN 128
#define BK 16

__global__ void __launch_bounds__(256)
proj_kernel(const int* __restrict__ X, const float* __restrict__ E,
            const float* __restrict__ Wxh, const float* __restrict__ bxh)
{
    __shared__ float As[BK][BM];
    __shared__ float Bs[BK][BN];
    __shared__ int   toks[BM];

    const int tid   = threadIdx.x;
    const int mtile = blockIdx.y;
    const int n     = mtile >> 4;
    const int l0    = (mtile & 15) * BM;
    const int j0    = blockIdx.x * BN;

    if (tid < BM) toks[tid] = X[n * LSTEPS + l0 + tid];
    __syncthreads();

    const int ty = tid >> 4;
    const int tx = tid & 15;

    unsigned long long acc[8][4];
#pragma unroll
    for (int i = 0; i < 8; i++)
#pragma unroll
        for (int j = 0; j < 4; j++) acc[i][j] = 0ULL;

    for (int k0 = 0; k0 < EMBED; k0 += BK) {
#pragma unroll
        for (int u = 0; u < 2; u++) {
            int f  = tid + u * 256;
            int m  = f & 127;
            int kq = f >> 7;
            float4 v = *(const float4*)&E[(size_t)toks[m] * EMBED + k0 + kq * 4];
            As[kq * 4 + 0][m] = v.x;
            As[kq * 4 + 1][m] = v.y;
            As[kq * 4 + 2][m] = v.z;
            As[kq * 4 + 3][m] = v.w;
        }
#pragma unroll
        for (int u = 0; u < 2; u++) {
            int f  = tid + u * 256;
            int kk = f >> 5;
            int jj = (f & 31) * 4;
            *(float4*)&Bs[kk][jj] =
                *(const float4*)&Wxh[(size_t)(k0 + kk) * HIDDEN + j0 + jj];
        }
        __syncthreads();
#pragma unroll
        for (int kk = 0; kk < BK; kk++) {
            float a[8];
            *(float4*)&a[0] = *(const float4*)&As[kk][ty * 8];
            *(float4*)&a[4] = *(const float4*)&As[kk][ty * 8 + 4];
            ulonglong2 b01 = *(const ulonglong2*)&Bs[kk][tx * 8];
            ulonglong2 b23 = *(const ulonglong2*)&Bs[kk][tx * 8 + 4];
            unsigned long long bp[4] = {b01.x, b01.y, b23.x, b23.y};
#pragma unroll
            for (int i = 0; i < 8; i++) {
                unsigned long long aa;
                PACK_F32X2(aa, a[i], a[i]);
#pragma unroll
                for (int j = 0; j < 4; j++)
                    FMA_F32X2(acc[i][j], aa, bp[j]);
            }
        }
        __syncthreads();
    }

    float bx[8];
#pragma unroll
    for (int q = 0; q < 8; q++) bx[q] = bxh[j0 + tx * 8 + q];

#pragma unroll
    for (int i = 0; i < 8; i++) {
        int l = l0 + ty * 8 + i;
        float* dst = g_xp + (size_t)l * (NB * HIDDEN) + n * HIDDEN + j0 + tx * 8;
        float r[8];
#pragma unroll
        for (int j = 0; j < 4; j++) {
            float lo, hi;
            UNPACK_F32X2(lo, hi, acc[i][j]);
            r[j * 2]     = lo + bx[j * 2];
            r[j * 2 + 1] = hi + bx[j * 2 + 1];
        }
        *(float4*)dst       = make_float4(r[0], r[1], r[2], r[3]);
        *(float4*)(dst + 4) = make_float4(r[4], r[5], r[6], r[7]);
    }
}

// ============================================================================
// Phase 2: persistent cluster RNN, 32 clusters x 4 CTAs, G=2 groups,
// PARTIAL-PUSH / CONSUMER-REDUCE design:
//   - each kg-warp pushes its raw float2 partial to all 4 peers' pbuf
//     right after its FMA loop (no reduce stage, no shfl, no 2nd bar);
//     lane0 release-arrives after __syncwarp (32 arrivals per group/step).
//   - consumer section starts with a local stage: 256 threads sum the 4
//     kg-partials + b + x, tanh, store single-buffer hbuf (2 cols each),
//     one __syncthreads, then compute.
// The 215-cyc DSMEM flights leave the critical path (overlap other section).
// W layout/split = R6-proven (REG_IT 20 / SMEM_IT 12).
// ============================================================================
#define CL       4
#define JSL      128
#define REG_IT   20                     // iters 0..19 from regs (80 ull)
#define SMEM_IT  12                     // iters 20..31 from smem (48 ull)
#define MB_CNT   (CL * 8)               // 8 warps x 4 CTAs arrive per group

struct SmemR {
    ulonglong2 Wsm[SMEM_IT * 2 * 256];  // [plane][tid] 16B lanes: 98304 B
    float pbuf[2][2][4][HIDDEN];        // [grp][buf][kg][jglobal] 32768 B
    float hbuf[2][HIDDEN];              // [grp][k] single-buffer   4096 B
    float bh[HIDDEN];                   // full bias                2048 B
    unsigned long long mb[2];           // per-group mbarrier
};
#define SMEMR_BYTES ((int)sizeof(SmemR))

__device__ __forceinline__ uint32_t smem_u32(const void* p) {
    uint32_t a;
    asm("{ .reg .u64 t; cvta.to.shared.u64 t, %1; cvt.u32.u64 %0, t; }"
        : "=r"(a) : "l"(p));
    return a;
}
__device__ __forceinline__ uint32_t mapa_u32(uint32_t a, uint32_t rank) {
    uint32_t r;
    asm("mapa.shared::cluster.u32 %0, %1, %2;" : "=r"(r) : "r"(a), "r"(rank));
    return r;
}
__device__ __forceinline__ void stc_f32x2(uint32_t a, float v0, float v1) {
    asm volatile("st.shared::cluster.v2.f32 [%0], {%1,%2};"
                 :: "r"(a), "f"(v0), "f"(v1) : "memory");
}
__device__ __forceinline__ void mbar_init(uint32_t a, uint32_t cnt) {
    asm volatile("mbarrier.init.shared.b64 [%0], %1;" :: "r"(a), "r"(cnt) : "memory");
}
__device__ __forceinline__ void mbar_arrive_remote(uint32_t a) {
    asm volatile("mbarrier.arrive.release.cluster.shared::cluster.b64 _, [%0];"
                 :: "r"(a) : "memory");
}
__device__ __forceinline__ void mbar_wait_parity(uint32_t a, uint32_t parity) {
    asm volatile(
        "{\n\t.reg .pred P;\n\t"
        "WL_%=:\n\t"
        "mbarrier.try_wait.parity.acquire.cluster.shared::cta.b64 P, [%0], %1, 0x989680;\n\t"
        "@!P bra WL_%=;\n\t}"
        :: "r"(a), "r"(parity) : "memory");
}
__device__ __forceinline__ void cluster_sync_() {
    asm volatile("barrier.cluster.arrive.aligned;" ::: "memory");
    asm volatile("barrier.cluster.wait.aligned;" ::: "memory");
}

// tanh = (e-1)/(e+1), e = 2^(2x*log2e); ~1e-6 abs err, branch-free.
__device__ __forceinline__ float fast_tanh(float x) {
    x = fminf(fmaxf(x, -15.0f), 15.0f);
    float e;
    asm("ex2.approx.f32 %0, %1;" : "=f"(e) : "f"(x * 2.8853900817779268f));
    float r;
    asm("rcp.approx.f32 %0, %1;" : "=f"(r) : "f"(e + 1.0f));
    return (e - 1.0f) * r;
}

extern __shared__ float smem_raw[];

__global__ void __cluster_dims__(CL, 1, 1) __launch_bounds__(256, 1)
rnn_kernel(const float* __restrict__ Whh, const float* __restrict__ bhh,
           float* __restrict__ out)
{
    SmemR* s = (SmemR*)smem_raw;
    const int tid  = threadIdx.x;
    const int rank = blockIdx.x;      // 0..3
    const int g    = blockIdx.y;      // 0..31
    const int j0   = rank * JSL;
    const int rowA = 2 * g;

    const int kg = tid >> 6;          // 0..3 : k in [128kg, +128)
    const int jp = tid & 63;          // j-pair: jcol = j0 + jp*2
    const int lane = tid & 31;

    // ---- W slice: 80 ull regs (iters 0..19) + 48 ull smem (iters 20..31) ----
    unsigned long long Wr0[2 * REG_IT], Wr1[2 * REG_IT];
    {
        const int kb   = kg * 128;
        const int jcol = j0 + jp * 2;
#pragma unroll
        for (int m = 0; m < 2 * REG_IT; m++) {
            int k = kb + m * 2;
            float2 w0 = *(const float2*)&Whh[(size_t)k * HIDDEN + jcol];
            float2 w1 = *(const float2*)&Whh[(size_t)(k + 1) * HIDDEN + jcol];
            PACK_F32X2(Wr0[m], w0.x, w1.x);
            PACK_F32X2(Wr1[m], w0.y, w1.y);
        }
#pragma unroll
        for (int i = 0; i < SMEM_IT; i++) {
            unsigned long long p0a, p0b, p1a, p1b;
#pragma unroll
            for (int q = 0; q < 2; q++) {
                int m = 2 * (REG_IT + i) + q;
                int k = kb + m * 2;
                float2 w0 = *(const float2*)&Whh[(size_t)k * HIDDEN + jcol];
                float2 w1 = *(const float2*)&Whh[(size_t)(k + 1) * HIDDEN + jcol];
                unsigned long long u0, u1;
                PACK_F32X2(u0, w0.x, w1.x);
                PACK_F32X2(u1, w0.y, w1.y);
                if (q == 0) { p0a = u0; p1a = u1; }
                else        { p0b = u0; p1b = u1; }
            }
            s->Wsm[(i * 2 + 0) * 256 + tid] = make_ulonglong2(p0a, p0b);
            s->Wsm[(i * 2 + 1) * 256 + tid] = make_ulonglong2(p1a, p1b);
        }
    }

    // ---- smem init: hbuf zero (h0 = 0), full bias ----
    for (int idx = tid; idx < 2 * HIDDEN; idx += 256)
        ((float*)s->hbuf)[idx] = 0.f;
    for (int idx = tid; idx < HIDDEN; idx += 256)
        s->bh[idx] = bhh[idx];

    const uint32_t s_base   = smem_u32(s);
    const uint32_t pbuf_off = smem_u32(&s->pbuf[0][0][0][0]) - s_base;
    const uint32_t mbA      = smem_u32(&s->mb[0]) - s_base;
    const uint32_t mbB      = smem_u32(&s->mb[1]) - s_base;

    uint32_t peer_base[CL];
#pragma unroll
    for (int r = 0; r < CL; r++) peer_base[r] = mapa_u32(s_base, (uint32_t)r);

    if (tid == 0) {
        mbar_init(s_base + mbA, MB_CNT);
        mbar_init(s_base + mbB, MB_CNT);
        asm volatile("fence.mbarrier_init.release.cluster;" ::: "memory");
    }
    __syncthreads();
    cluster_sync_();   // W/hbuf/bh/mbar visible cluster-wide

    // tanh-stage columns: jg1 = tid, jg2 = tid + 256 (both rows)
    const int jg1 = tid;
    const int jg2 = tid + 256;

    // x pointers: x[t][row][jg]
    const size_t XS = (size_t)NB * HIDDEN;
    const float* pA1 = g_xp + (size_t)rowA * HIDDEN + jg1;
    const float* pA2 = pA1 + 256;
    const float* pB1 = pA1 + HIDDEN;      // rowB = rowA + 1
    const float* pB2 = pB1 + 256;

    float cA1 = 0.f, cA2 = 0.f, cB1 = 0.f, cB2 = 0.f;   // x_{t-1} (unused at t=0)

    // push offset base (floats): pbuf[grp][buf][kg][j0 + 2jp]
    const uint32_t push_col = (uint32_t)(kg * HIDDEN + j0 + 2 * jp);

    for (int t = 0; t <= LSTEPS; t++) {
        const bool first = (t == 0);
        const bool last  = (t == LSTEPS);
        const int  pbw   = t & 1;            // producer buf at step t
        const int  pbr   = (t - 1) & 1;      // consumer buf at step t
        const uint32_t pw = (uint32_t)((t - 1) & 1);  // wait parity

        // prefetch x_t (used at t+1)
        float nA1 = 0.f, nA2 = 0.f, nB1 = 0.f, nB2 = 0.f;
        if (!last) {
            nA1 = __ldcs(pA1); nA2 = __ldcs(pA2);
            nB1 = __ldcs(pB1); nB2 = __ldcs(pB2);
            pA1 += XS; pA2 += XS; pB1 += XS; pB2 += XS;
        }

#pragma unroll 1
        for (int grp = 0; grp < 2; grp++) {
            const uint32_t mb_off = grp ? mbB : mbA;

            if (!first) {
                mbar_wait_parity(s_base + mb_off, pw);
                // ---- consumer stage: sum 4 partials + b + x, tanh ----
                const float* pb = &s->pbuf[grp][pbr][0][0];
                float x1 = grp ? cB1 : cA1;
                float x2 = grp ? cB2 : cA2;
                float s1 = s->bh[jg1] + x1
                         + pb[jg1] + pb[HIDDEN + jg1]
                         + pb[2 * HIDDEN + jg1] + pb[3 * HIDDEN + jg1];
                float s2 = s->bh[jg2] + x2
                         + pb[jg2] + pb[HIDDEN + jg2]
                         + pb[2 * HIDDEN + jg2] + pb[3 * HIDDEN + jg2];
                float h1 = fast_tanh(s1);
                float h2 = fast_tanh(s2);
                if (last) {
                    out[(rowA + grp) * HIDDEN + jg1] = h1;
                    out[(rowA + grp) * HIDDEN + jg2] = h2;
                } else {
                    s->hbuf[grp][jg1] = h1;
                    s->hbuf[grp][jg2] = h2;
                }
            }

            if (!last) {
                __syncthreads();   // hbuf[grp] ready for all warps

                // ---- inner product: 1 row x 2 cols x 128 k ----
                const ulonglong2* hv =
                    (const ulonglong2*)&s->hbuf[grp][kg * 128];
                const ulonglong2* WsmT = &s->Wsm[tid];
                unsigned long long a0 = 0ULL, a1 = 0ULL;
#pragma unroll
                for (int i = 0; i < REG_IT; i++) {
                    ulonglong2 h = hv[i];
                    FMA_F32X2(a0, Wr0[2 * i],     h.x);
                    FMA_F32X2(a0, Wr0[2 * i + 1], h.y);
                    FMA_F32X2(a1, Wr1[2 * i],     h.x);
                    FMA_F32X2(a1, Wr1[2 * i + 1], h.y);
                }
#pragma unroll
                for (int i = 0; i < SMEM_IT; i++) {
                    ulonglong2 h  = hv[REG_IT + i];
                    ulonglong2 w0 = WsmT[(i * 2 + 0) * 256];
                    ulonglong2 w1 = WsmT[(i * 2 + 1) * 256];
                    FMA_F32X2(a0, w0.x, h.x);
                    FMA_F32X2(a0, w0.y, h.y);
                    FMA_F32X2(a1, w1.x, h.x);
                    FMA_F32X2(a1, w1.y, h.y);
                }
                float lo, hi, f0, f1;
                UNPACK_F32X2(lo, hi, a0); f0 = lo + hi;
                UNPACK_F32X2(lo, hi, a1); f1 = lo + hi;

                // ---- push raw partial to all 4 peers, then release-arrive ----
                const uint32_t off = pbuf_off +
                    (uint32_t)(((grp * 2 + pbw) * 4) * HIDDEN + push_col) * 4;
#pragma unroll
                for (int r = 0; r < CL; r++)
                    stc_f32x2(peer_base[r] + off, f0, f1);
                __syncwarp();
                if (lane == 0) {
#pragma unroll
                    for (int r = 0; r < CL; r++)
                        mbar_arrive_remote(peer_base[r] + mb_off);
                }
            }
        }

        cA1 = nA1; cA2 = nA2; cB1 = nB1; cB2 = nB2;
    }
}

// ============================================================================
extern "C" void kernel_launch(void* const* d_in, const int* in_sizes, int n_in,
                              void* d_out, int out_size)
{
    const int*   X   = (const int*)d_in[0];
    const float* E   = (const float*)d_in[1];
    const float* Whh = (const float*)d_in[2];
    const float* bhh = (const float*)d_in[3];
    const float* Wxh = (const float*)d_in[4];
    const float* bxh = (const float*)d_in[5];
    float* out = (float*)d_out;

    cudaFuncSetAttribute(rnn_kernel,
                         cudaFuncAttributeMaxDynamicSharedMemorySize,
                         SMEMR_BYTES);

    proj_kernel<<<dim3(4, 1024), 256>>>(X, E, Wxh, bxh);
    rnn_kernel<<<dim3(CL, NB / 2), 256, SMEMR_BYTES>>>(Whh, bhh, out);
}

// round 15
// speedup vs baseline: 1.8301x; 1.8301x over previous
#include <cuda_runtime.h>
#include <cstdint>
#include <math.h>

#define EMBED   256
#define HIDDEN  512
#define NB      64
#define LSTEPS  2048

// xp[t][n][h] scratch: 2048*64*512 floats = 256MB
__device__ float g_xp[(size_t)LSTEPS * NB * HIDDEN];

// ---- packed f32x2 helpers (Blackwell) ----
#define FMA_F32X2(acc, a, b) \
    asm("fma.rn.f32x2 %0, %1, %2, %0;" : "+l"(acc) : "l"(a), "l"(b))
#define PACK_F32X2(out, lo, hi) \
    asm("mov.b64 %0, {%1, %2};" : "=l"(out) : "f"(lo), "f"(hi))
#define UNPACK_F32X2(lo, hi, in) \
    asm("mov.b64 {%0, %1}, %2;" : "=f"(lo), "=f"(hi) : "l"(in))

__device__ __forceinline__ uint32_t smem_u32(const void* p) {
    uint32_t a;
    asm("{ .reg .u64 t; cvta.to.shared.u64 t, %1; cvt.u32.u64 %0, t; }"
        : "=r"(a) : "l"(p));
    return a;
}
__device__ __forceinline__ void cp_async16(uint32_t saddr, const void* g) {
    asm volatile("cp.async.ca.shared.global [%0], [%1], 16;"
                 :: "r"(saddr), "l"(g));
}
#define CP_COMMIT() asm volatile("cp.async.commit_group;" ::: "memory")
#define CP_WAIT0()  asm volatile("cp.async.wait_group 0;" ::: "memory")

// ============================================================================
// Phase 1: xp[l][n][j] = b_xh[j] + sum_d E[X[n][l]][d] * W_xh[d][j]
// v2: double-buffered tiles (cp.async for Wxh, reg-staged LDG for gathered E),
// ONE __syncthreads per k-iter, streaming stores for the 256MB output.
// ============================================================================
#define BM 128
#define BN 128
#define BK 16

struct alignas(16) PSmem {
    float As[2][BK][BM];
    float Bs[2][BK][BN];
    int   toks[BM];
};

__global__ void __launch_bounds__(256)
proj_kernel(const int* __restrict__ X, const float* __restrict__ E,
            const float* __restrict__ Wxh, const float* __restrict__ bxh)
{
    __shared__ PSmem ps;

    const int tid   = threadIdx.x;
    const int mtile = blockIdx.y;
    const int n     = mtile >> 4;
    const int l0    = (mtile & 15) * BM;
    const int j0    = blockIdx.x * BN;

    if (tid < BM) ps.toks[tid] = X[n * LSTEPS + l0 + tid];
    __syncthreads();

    const int ty = tid >> 4;
    const int tx = tid & 15;

    // per-thread load coordinates (two chunks u=0,1)
    const int m0  = tid & 127;          // u=0: f = tid
    const int kq0 = tid >> 7;           // 0..1
    const int m1  = m0;                 // u=1: f = tid+256
    const int kq1 = kq0 + 2;            // 2..3
    const int bkk0 = tid >> 5;          // B: u=0 kk 0..7
    const int bjj0 = (tid & 31) * 4;
    const int bkk1 = bkk0 + 8;          // u=1 kk 8..15
    const int bjj1 = bjj0;

    unsigned long long acc[8][4];
#pragma unroll
    for (int i = 0; i < 8; i++)
#pragma unroll
        for (int j = 0; j < 4; j++) acc[i][j] = 0ULL;

    // ---- prologue: tile 0 into buffer 0 ----
    {
        float4 a0 = *(const float4*)&E[(size_t)ps.toks[m0] * EMBED + kq0 * 4];
        float4 a1 = *(const float4*)&E[(size_t)ps.toks[m1] * EMBED + kq1 * 4];
        ps.As[0][kq0 * 4 + 0][m0] = a0.x;
        ps.As[0][kq0 * 4 + 1][m0] = a0.y;
        ps.As[0][kq0 * 4 + 2][m0] = a0.z;
        ps.As[0][kq0 * 4 + 3][m0] = a0.w;
        ps.As[0][kq1 * 4 + 0][m1] = a1.x;
        ps.As[0][kq1 * 4 + 1][m1] = a1.y;
        ps.As[0][kq1 * 4 + 2][m1] = a1.z;
        ps.As[0][kq1 * 4 + 3][m1] = a1.w;
        cp_async16(smem_u32(&ps.Bs[0][bkk0][bjj0]),
                   &Wxh[(size_t)bkk0 * HIDDEN + j0 + bjj0]);
        cp_async16(smem_u32(&ps.Bs[0][bkk1][bjj1]),
                   &Wxh[(size_t)bkk1 * HIDDEN + j0 + bjj1]);
        CP_COMMIT();
        CP_WAIT0();
    }
    __syncthreads();

    int buf = 0;
#pragma unroll 1
    for (int it = 0; it < EMBED / BK; it++) {
        const int  k0       = it * BK;
        const bool has_next = (it < EMBED / BK - 1);
        const int  nxt      = buf ^ 1;

        // issue next-tile loads (overlap with compute)
        float4 a0n, a1n;
        if (has_next) {
            const int kn = k0 + BK;
            a0n = *(const float4*)&E[(size_t)ps.toks[m0] * EMBED + kn + kq0 * 4];
            a1n = *(const float4*)&E[(size_t)ps.toks[m1] * EMBED + kn + kq1 * 4];
            cp_async16(smem_u32(&ps.Bs[nxt][bkk0][bjj0]),
                       &Wxh[(size_t)(kn + bkk0) * HIDDEN + j0 + bjj0]);
            cp_async16(smem_u32(&ps.Bs[nxt][bkk1][bjj1]),
                       &Wxh[(size_t)(kn + bkk1) * HIDDEN + j0 + bjj1]);
            CP_COMMIT();
        }

        // compute on current buffer
#pragma unroll
        for (int kk = 0; kk < BK; kk++) {
            float a[8];
            *(float4*)&a[0] = *(const float4*)&ps.As[buf][kk][ty * 8];
            *(float4*)&a[4] = *(const float4*)&ps.As[buf][kk][ty * 8 + 4];
            ulonglong2 b01 = *(const ulonglong2*)&ps.Bs[buf][kk][tx * 8];
            ulonglong2 b23 = *(const ulonglong2*)&ps.Bs[buf][kk][tx * 8 + 4];
            unsigned long long bp[4] = {b01.x, b01.y, b23.x, b23.y};
#pragma unroll
            for (int i = 0; i < 8; i++) {
                unsigned long long aa;
                PACK_F32X2(aa, a[i], a[i]);
#pragma unroll
                for (int j = 0; j < 4; j++)
                    FMA_F32X2(acc[i][j], aa, bp[j]);
            }
        }

        if (has_next) {
            ps.As[nxt][kq0 * 4 + 0][m0] = a0n.x;
            ps.As[nxt][kq0 * 4 + 1][m0] = a0n.y;
            ps.As[nxt][kq0 * 4 + 2][m0] = a0n.z;
            ps.As[nxt][kq0 * 4 + 3][m0] = a0n.w;
            ps.As[nxt][kq1 * 4 + 0][m1] = a1n.x;
            ps.As[nxt][kq1 * 4 + 1][m1] = a1n.y;
            ps.As[nxt][kq1 * 4 + 2][m1] = a1n.z;
            ps.As[nxt][kq1 * 4 + 3][m1] = a1n.w;
            CP_WAIT0();
            __syncthreads();
            buf = nxt;
        }
    }

    float bx[8];
#pragma unroll
    for (int q = 0; q < 8; q++) bx[q] = bxh[j0 + tx * 8 + q];

#pragma unroll
    for (int i = 0; i < 8; i++) {
        int l = l0 + ty * 8 + i;
        float* dst = g_xp + (size_t)l * (NB * HIDDEN) + n * HIDDEN + j0 + tx * 8;
        float r[8];
#pragma unroll
        for (int j = 0; j < 4; j++) {
            float lo, hi;
            UNPACK_F32X2(lo, hi, acc[i][j]);
            r[j * 2]     = lo + bx[j * 2];
            r[j * 2 + 1] = hi + bx[j * 2 + 1];
        }
        __stcs((float4*)dst,       make_float4(r[0], r[1], r[2], r[3]));
        __stcs((float4*)(dst + 4), make_float4(r[4], r[5], r[6], r[7]));
    }
}

// ============================================================================
// Phase 2: persistent cluster RNN — R6 (4799us run) VERBATIM.
// 32 clusters x 4 CTAs, G=2 groups, W 80 ull regs + 48 ull smem.
// ============================================================================
#define CL       4
#define JSL      128
#define REG_IT   20                     // iters 0..19 from regs (80 ull)
#define SMEM_IT  12                     // iters 20..31 from smem (48 ull)

struct SmemR {
    ulonglong2 Wsm[SMEM_IT * 2 * 256];  // [plane][tid] 16B lanes: 98304 B
    float hbuf[2][2][HIDDEN];           // [group][buf][j]         8192 B
    float red[2][4][JSL];               // [group][kg][j]          4096 B
    float bh[JSL];                      //                         512 B
    unsigned long long mb[2];           // per-group mbarrier
};
#define SMEMR_BYTES ((int)sizeof(SmemR))

__device__ __forceinline__ uint32_t mapa_u32(uint32_t a, uint32_t rank) {
    uint32_t r;
    asm("mapa.shared::cluster.u32 %0, %1, %2;" : "=r"(r) : "r"(a), "r"(rank));
    return r;
}
__device__ __forceinline__ void stc_b32(uint32_t a, float v) {
    asm volatile("st.shared::cluster.b32 [%0], %1;"
                 :: "r"(a), "r"(__float_as_uint(v)) : "memory");
}
__device__ __forceinline__ void mbar_init(uint32_t a, uint32_t cnt) {
    asm volatile("mbarrier.init.shared.b64 [%0], %1;" :: "r"(a), "r"(cnt) : "memory");
}
__device__ __forceinline__ void mbar_arrive_remote(uint32_t a) {
    asm volatile("mbarrier.arrive.release.cluster.shared::cluster.b64 _, [%0];"
                 :: "r"(a) : "memory");
}
__device__ __forceinline__ void mbar_wait_parity(uint32_t a, uint32_t parity) {
    asm volatile(
        "{\n\t.reg .pred P;\n\t"
        "WL_%=:\n\t"
        "mbarrier.try_wait.parity.acquire.cluster.shared::cta.b64 P, [%0], %1, 0x989680;\n\t"
        "@!P bra WL_%=;\n\t}"
        :: "r"(a), "r"(parity) : "memory");
}
__device__ __forceinline__ void cluster_sync_() {
    asm volatile("barrier.cluster.arrive.aligned;" ::: "memory");
    asm volatile("barrier.cluster.wait.aligned;" ::: "memory");
}

// tanh = (e-1)/(e+1), e = 2^(2x*log2e); ~1e-6 abs err, branch-free.
__device__ __forceinline__ float fast_tanh(float x) {
    x = fminf(fmaxf(x, -15.0f), 15.0f);
    float e;
    asm("ex2.approx.f32 %0, %1;" : "=f"(e) : "f"(x * 2.8853900817779268f));
    float r;
    asm("rcp.approx.f32 %0, %1;" : "=f"(r) : "f"(e + 1.0f));
    return (e - 1.0f) * r;
}

extern __shared__ float smem_raw[];

__global__ void __cluster_dims__(CL, 1, 1) __launch_bounds__(256, 1)
rnn_kernel(const float* __restrict__ Whh, const float* __restrict__ bhh,
           float* __restrict__ out)
{
    SmemR* s = (SmemR*)smem_raw;
    const int tid  = threadIdx.x;
    const int rank = blockIdx.x;      // 0..3
    const int g    = blockIdx.y;      // 0..31
    const int j0   = rank * JSL;
    const int rowA = 2 * g;
    const int rowB = 2 * g + 1;

    const int kg = tid >> 6;          // 0..3 : k in [128kg, +128)
    const int jp = tid & 63;          // j-pair: jcol = j0 + jp*2

    // ---- W slice: 80 ull regs (iters 0..19) + 48 ull smem (iters 20..31) ----
    unsigned long long Wr0[2 * REG_IT], Wr1[2 * REG_IT];
    {
        const int kb   = kg * 128;
        const int jcol = j0 + jp * 2;
#pragma unroll
        for (int m = 0; m < 2 * REG_IT; m++) {
            int k = kb + m * 2;
            float2 w0 = *(const float2*)&Whh[(size_t)k * HIDDEN + jcol];
            float2 w1 = *(const float2*)&Whh[(size_t)(k + 1) * HIDDEN + jcol];
            PACK_F32X2(Wr0[m], w0.x, w1.x);
            PACK_F32X2(Wr1[m], w0.y, w1.y);
        }
#pragma unroll
        for (int i = 0; i < SMEM_IT; i++) {
            unsigned long long p0a, p0b, p1a, p1b;
#pragma unroll
            for (int q = 0; q < 2; q++) {
                int m = 2 * (REG_IT + i) + q;
                int k = kb + m * 2;
                float2 w0 = *(const float2*)&Whh[(size_t)k * HIDDEN + jcol];
                float2 w1 = *(const float2*)&Whh[(size_t)(k + 1) * HIDDEN + jcol];
                unsigned long long u0, u1;
                PACK_F32X2(u0, w0.x, w1.x);
                PACK_F32X2(u1, w0.y, w1.y);
                if (q == 0) { p0a = u0; p1a = u1; }
                else        { p0b = u0; p1b = u1; }
            }
            s->Wsm[(i * 2 + 0) * 256 + tid] = make_ulonglong2(p0a, p0b);
            s->Wsm[(i * 2 + 1) * 256 + tid] = make_ulonglong2(p1a, p1b);
        }
    }

    // ---- smem init ----
    for (int idx = tid; idx < 2 * 2 * HIDDEN; idx += 256)
        ((float*)s->hbuf)[idx] = 0.f;
    if (tid < JSL) s->bh[tid] = bhh[j0 + tid];

    const uint32_t s_base = smem_u32(s);
    const uint32_t hbA    = smem_u32(&s->hbuf[0][0][0]) - s_base;
    const uint32_t hbB    = smem_u32(&s->hbuf[1][0][0]) - s_base;
    const uint32_t mbA    = smem_u32(&s->mb[0]) - s_base;
    const uint32_t mbB    = smem_u32(&s->mb[1]) - s_base;

    uint32_t peer_base[CL];
#pragma unroll
    for (int r = 0; r < CL; r++) peer_base[r] = mapa_u32(s_base, (uint32_t)r);

    if (tid == 0) {
        mbar_init(s_base + mbA, CL);
        mbar_init(s_base + mbB, CL);
        asm volatile("fence.mbarrier_init.release.cluster;" ::: "memory");
    }
    __syncthreads();
    cluster_sync_();   // W/h/bh/mbar visible cluster-wide

    // reduce/push role: tid<128 handles j = tid
    const int rj = tid & 127;
    const bool is_red = (tid < JSL);

    const size_t xstride = (size_t)NB * HIDDEN;
    const float* xpA = g_xp + (size_t)rowA * HIDDEN + j0 + rj;
    const float* xpB = g_xp + (size_t)rowB * HIDDEN + j0 + rj;

    float xA = __ldcs(xpA), xB = __ldcs(xpB);
    const float* xAn = xpA + xstride;
    const float* xBn = xpB + xstride;

    const ulonglong2* WsmT = &s->Wsm[tid];     // plane p at WsmT[p*256]

    for (int t = 0; t < LSTEPS; t++) {
        const int cur = t & 1;
        const int nxt = cur ^ 1;
        const uint32_t pw = (uint32_t)((t & 1) ^ 1);   // parity of step t-1
        const bool last = (t == LSTEPS - 1);
        float xAnx = last ? 0.f : __ldcs(xAn);
        float xBnx = last ? 0.f : __ldcs(xBn);

#pragma unroll 1
        for (int grp = 0; grp < 2; grp++) {
            const uint32_t mb_off = grp ? mbB : mbA;
            const uint32_t hb_off = grp ? hbB : hbA;

            if (t) mbar_wait_parity(s_base + mb_off, pw);

            // ---- inner product: 1 row x 2 cols x 128 k ----
            const ulonglong2* hv =
                (const ulonglong2*)&s->hbuf[grp][cur][kg * 128];
            unsigned long long a0 = 0ULL, a1 = 0ULL;
#pragma unroll
            for (int i = 0; i < REG_IT; i++) {
                ulonglong2 h = hv[i];
                FMA_F32X2(a0, Wr0[2 * i],     h.x);
                FMA_F32X2(a0, Wr0[2 * i + 1], h.y);
                FMA_F32X2(a1, Wr1[2 * i],     h.x);
                FMA_F32X2(a1, Wr1[2 * i + 1], h.y);
            }
#pragma unroll
            for (int i = 0; i < SMEM_IT; i++) {
                ulonglong2 h  = hv[REG_IT + i];
                ulonglong2 w0 = WsmT[(i * 2 + 0) * 256];
                ulonglong2 w1 = WsmT[(i * 2 + 1) * 256];
                FMA_F32X2(a0, w0.x, h.x);
                FMA_F32X2(a0, w0.y, h.y);
                FMA_F32X2(a1, w1.x, h.x);
                FMA_F32X2(a1, w1.y, h.y);
            }
            {
                float lo, hi, f0, f1;
                UNPACK_F32X2(lo, hi, a0); f0 = lo + hi;
                UNPACK_F32X2(lo, hi, a1); f1 = lo + hi;
                *(float2*)&s->red[grp][kg][jp * 2] = make_float2(f0, f1);
            }
            __syncthreads();

            // ---- reduce + tanh + push (tid < 128) ----
            if (is_red) {
                float xr = grp ? xB : xA;
                float sum = s->bh[rj] + xr
                          + s->red[grp][0][rj] + s->red[grp][1][rj]
                          + s->red[grp][2][rj] + s->red[grp][3][rj];
                float hn = fast_tanh(sum);

                if (last) {
                    out[(rowA + grp) * HIDDEN + j0 + rj] = hn;
                } else {
                    const uint32_t off = hb_off +
                        (uint32_t)((nxt * HIDDEN + j0 + rj) * 4);
#pragma unroll
                    for (int r = 0; r < CL; r++)
                        stc_b32(peer_base[r] + off, hn);
                }
            }
            __syncthreads();
            if (!last && tid < CL)
                mbar_arrive_remote(peer_base[tid] + mb_off);
        }

        xA = xAnx; xB = xBnx;
        xAn += xstride; xBn += xstride;
    }
}

// ============================================================================
extern "C" void kernel_launch(void* const* d_in, const int* in_sizes, int n_in,
                              void* d_out, int out_size)
{
    const int*   X   = (const int*)d_in[0];
    const float* E   = (const float*)d_in[1];
    const float* Whh = (const float*)d_in[2];
    const float* bhh = (const float*)d_in[3];
    const float* Wxh = (const float*)d_in[4];
    const float* bxh = (const float*)d_in[5];
    float* out = (float*)d_out;

    cudaFuncSetAttribute(rnn_kernel,
                         cudaFuncAttributeMaxDynamicSharedMemorySize,
                         SMEMR_BYTES);

    proj_kernel<<<dim3(4, 1024), 256>>>(X, E, Wxh, bxh);
    rnn_kernel<<<dim3(CL, NB / 2), 256, SMEMR_BYTES>>>(Whh, bhh, out);
}